// round 6
// baseline (speedup 1.0000x reference)
#include <cuda_runtime.h>
#include <math.h>

#define N_TOK 16384
#define DDIM  2048
#define NEXP  8

#define BM 128
#define BN 128
#define BK 8

// routing scratch (device globals: allocation-free per harness rules)
__device__ int   g_cnt[NEXP];
__device__ int   g_tok[NEXP * N_TOK];    // value = 2*token + slot
__device__ float g_wt [NEXP * N_TOK];
__device__ float g_scr[(size_t)2 * N_TOK * DDIM];  // 256 MB scatter buffer

__global__ void zero_cnt_kernel() {
    if (threadIdx.x < NEXP) g_cnt[threadIdx.x] = 0;
}

// One warp per token: 8 gate logits, top-2, softmax, append to expert lists.
__global__ __launch_bounds__(256) void gate_route_kernel(
    const float* __restrict__ x, const float* __restrict__ gw)
{
    int warp = threadIdx.x >> 5, lane = threadIdx.x & 31;
    int n = blockIdx.x * 8 + warp;
    if (n >= N_TOK) return;
    const float* xr = x + (size_t)n * DDIM;

    float acc[NEXP];
#pragma unroll
    for (int e = 0; e < NEXP; e++) acc[e] = 0.f;

    for (int d = lane; d < DDIM; d += 32) {
        float xv = xr[d];
        const float* g = gw + d * NEXP;
#pragma unroll
        for (int e = 0; e < NEXP; e++) acc[e] = fmaf(xv, g[e], acc[e]);
    }
#pragma unroll
    for (int e = 0; e < NEXP; e++) {
#pragma unroll
        for (int o = 16; o > 0; o >>= 1)
            acc[e] += __shfl_xor_sync(0xFFFFFFFFu, acc[e], o);
    }
    if (lane == 0) {
        // top-1 (lowest index wins ties, matching jax.lax.top_k)
        int e0 = 0; float l0 = acc[0];
#pragma unroll
        for (int e = 1; e < NEXP; e++) if (acc[e] > l0) { l0 = acc[e]; e0 = e; }
        // top-2
        int e1 = -1; float l1 = -INFINITY;
#pragma unroll
        for (int e = 0; e < NEXP; e++)
            if (e != e0 && acc[e] > l1) { l1 = acc[e]; e1 = e; }
        // softmax over [l0, l1], l0 >= l1
        float t  = expf(l1 - l0);
        float inv = 1.f / (1.f + t);
        float w0 = inv, w1 = t * inv;

        int p0 = atomicAdd(&g_cnt[e0], 1);
        g_tok[e0 * N_TOK + p0] = 2 * n;
        g_wt [e0 * N_TOK + p0] = w0;
        int p1 = atomicAdd(&g_cnt[e1], 1);
        g_tok[e1 * N_TOK + p1] = 2 * n + 1;
        g_wt [e1 * N_TOK + p1] = w1;
    }
}

// Grouped GEMM: for expert e, rows = gathered tokens, cols = output dim.
// Tile 128x128, K-step 8, 256 threads, 8x8 micro-tile, double-buffered smem.
// Epilogue: scr[2n+slot][h] = w * (acc + bias[e][h])   (no atomics)
__global__ __launch_bounds__(256, 1) void moe_gemm_kernel(
    const float* __restrict__ x,
    const float* __restrict__ ew,
    const float* __restrict__ eb)
{
    int e   = blockIdx.z;
    int cnt = g_cnt[e];
    int m0  = blockIdx.y * BM;
    if (m0 >= cnt) return;
    int n0  = blockIdx.x * BN;

    __shared__ float As[2][BK][BM + 4];   // 2 x 8 x 132
    __shared__ float Bs[2][BK][BN + 4];
    __shared__ int   toks[BM];
    __shared__ float wts [BM];

    int t = threadIdx.x;
    if (t < BM) {
        int r = m0 + t;
        bool ok = (r < cnt);
        toks[t] = ok ? g_tok[e * N_TOK + r] : 0;
        wts [t] = ok ? g_wt [e * N_TOK + r] : 0.f;
    }
    __syncthreads();

    const float* W = ew + (size_t)e * DDIM * DDIM;

    // global load assignment
    int ra = t >> 1, ca = (t & 1) * 4;          // A: row ra, k-offset ca
    int kb = t >> 5, cb = (t & 31) * 4;         // B: k-row kb, col cb
    const float* aptr = x + (size_t)(toks[ra] >> 1) * DDIM + ca;
    const float* bptr = W + (size_t)kb * DDIM + n0 + cb;

    // compute assignment: 8x8 micro-tile
    int tx = t & 15, ty = t >> 4;

    // prologue: tile 0 -> buffer 0
    {
        float4 av = *(const float4*)aptr;
        float4 bv = *(const float4*)bptr;
        As[0][ca + 0][ra] = av.x; As[0][ca + 1][ra] = av.y;
        As[0][ca + 2][ra] = av.z; As[0][ca + 3][ra] = av.w;
        *(float4*)&Bs[0][kb][cb] = bv;
    }
    __syncthreads();

    float acc[8][8];
#pragma unroll
    for (int i = 0; i < 8; i++)
#pragma unroll
        for (int j = 0; j < 8; j++) acc[i][j] = 0.f;

    const int NT = DDIM / BK;   // 256
    for (int it = 0; it < NT; it++) {
        int buf = it & 1;
        float4 an, bn;
        bool hasnext = (it + 1 < NT);
        if (hasnext) {
            an = *(const float4*)(aptr + (it + 1) * BK);
            bn = *(const float4*)(bptr + (size_t)(it + 1) * BK * DDIM);
        }

#pragma unroll
        for (int k = 0; k < BK; k++) {
            float4 a4l = *(const float4*)&As[buf][k][ty * 8];
            float4 a4h = *(const float4*)&As[buf][k][ty * 8 + 4];
            float4 b4l = *(const float4*)&Bs[buf][k][tx * 8];
            float4 b4h = *(const float4*)&Bs[buf][k][tx * 8 + 4];
            float ar[8] = {a4l.x, a4l.y, a4l.z, a4l.w,
                           a4h.x, a4h.y, a4h.z, a4h.w};
            float br[8] = {b4l.x, b4l.y, b4l.z, b4l.w,
                           b4h.x, b4h.y, b4h.z, b4h.w};
#pragma unroll
            for (int i = 0; i < 8; i++)
#pragma unroll
                for (int j = 0; j < 8; j++)
                    acc[i][j] = fmaf(ar[i], br[j], acc[i][j]);
        }

        if (hasnext) {
            int nb = buf ^ 1;
            As[nb][ca + 0][ra] = an.x; As[nb][ca + 1][ra] = an.y;
            As[nb][ca + 2][ra] = an.z; As[nb][ca + 3][ra] = an.w;
            *(float4*)&Bs[nb][kb][cb] = bn;
            __syncthreads();
        }
    }

    // epilogue
    float4 bias0 = *(const float4*)(eb + (size_t)e * DDIM + n0 + tx * 8);
    float4 bias1 = *(const float4*)(eb + (size_t)e * DDIM + n0 + tx * 8 + 4);
    float bb[8] = {bias0.x, bias0.y, bias0.z, bias0.w,
                   bias1.x, bias1.y, bias1.z, bias1.w};
#pragma unroll
    for (int i = 0; i < 8; i++) {
        int lr = ty * 8 + i;
        int r  = m0 + lr;
        if (r < cnt) {
            int   v = toks[lr];
            float w = wts [lr];
            float* dst = g_scr + (size_t)v * DDIM + n0 + tx * 8;
            float4 o0, o1;
            o0.x = w * (acc[i][0] + bb[0]); o0.y = w * (acc[i][1] + bb[1]);
            o0.z = w * (acc[i][2] + bb[2]); o0.w = w * (acc[i][3] + bb[3]);
            o1.x = w * (acc[i][4] + bb[4]); o1.y = w * (acc[i][5] + bb[5]);
            o1.z = w * (acc[i][6] + bb[6]); o1.w = w * (acc[i][7] + bb[7]);
            *(float4*)(dst)     = o0;
            *(float4*)(dst + 4) = o1;
        }
    }
}

// out[n] = scr[2n] + scr[2n+1]  (weights & bias already applied)
__global__ __launch_bounds__(256) void combine_kernel(float* __restrict__ out)
{
    size_t i = (size_t)blockIdx.x * 256 + threadIdx.x;  // float4 index
    size_t n = i >> 9;            // DDIM/4 = 512 float4 per row
    size_t h = (i & 511) * 4;
    const float4 a = *(const float4*)(g_scr + (2 * n)     * (size_t)DDIM + h);
    const float4 b = *(const float4*)(g_scr + (2 * n + 1) * (size_t)DDIM + h);
    float4 o;
    o.x = a.x + b.x; o.y = a.y + b.y; o.z = a.z + b.z; o.w = a.w + b.w;
    *(float4*)(out + n * (size_t)DDIM + h) = o;
}

extern "C" void kernel_launch(void* const* d_in, const int* in_sizes, int n_in,
                              void* d_out, int out_size)
{
    const float* inputs   = (const float*)d_in[0];  // [N, D]
    const float* gate_w   = (const float*)d_in[1];  // [D, E]
    const float* expert_w = (const float*)d_in[2];  // [E, D, D]
    const float* expert_b = (const float*)d_in[3];  // [E, D]
    float* out = (float*)d_out;

    zero_cnt_kernel<<<1, 32>>>();
    gate_route_kernel<<<N_TOK / 8, 256>>>(inputs, gate_w);
    dim3 ggrid(DDIM / BN, N_TOK / BM, NEXP);
    moe_gemm_kernel<<<ggrid, 256>>>(inputs, expert_w, expert_b);
    combine_kernel<<<(N_TOK * (DDIM / 4)) / 256, 256>>>(out);
}

// round 15
// speedup vs baseline: 1.4387x; 1.4387x over previous
#include <cuda_runtime.h>
#include <cuda_bf16.h>
#include <math.h>
#include <stdint.h>

#define N_TOK 16384
#define DDIM  2048
#define NEXP  8

#define TM 128
#define TN 128
#define BK 16
#define NT (DDIM / BK)   // 128 chunks

// ---- device scratch ----
__device__ int   g_cnt[NEXP];
__device__ int   g_tok[NEXP * N_TOK];    // value = 2*token + slot
__device__ float g_wt [NEXP * N_TOK];
__device__ float g_scr[(size_t)2 * N_TOK * DDIM];
__device__ __nv_bfloat16 g_xhi[(size_t)N_TOK * DDIM];
__device__ __nv_bfloat16 g_xlo[(size_t)N_TOK * DDIM];
__device__ __nv_bfloat16 g_whi[(size_t)NEXP * DDIM * DDIM];  // [e][n][k]
__device__ __nv_bfloat16 g_wlo[(size_t)NEXP * DDIM * DDIM];

__device__ __forceinline__ uint32_t smem_u32(const void* p) {
    uint32_t a;
    asm("{ .reg .u64 t; cvta.to.shared.u64 t, %1; cvt.u32.u64 %0, t; }" : "=r"(a) : "l"(p));
    return a;
}

#define LDSM4(r0, r1, r2, r3, a)                                        \
    asm volatile("ldmatrix.sync.aligned.m8n8.x4.shared.b16 "            \
                 "{%0,%1,%2,%3}, [%4];"                                 \
                 : "=r"(r0), "=r"(r1), "=r"(r2), "=r"(r3) : "r"(a))

#define MMA16816(c, a0, a1, a2, a3, b0, b1)                             \
    asm volatile("mma.sync.aligned.m16n8k16.row.col.f32.bf16.bf16.f32 " \
                 "{%0,%1,%2,%3}, {%4,%5,%6,%7}, {%8,%9}, {%0,%1,%2,%3};"\
                 : "+f"((c)[0]), "+f"((c)[1]), "+f"((c)[2]), "+f"((c)[3])\
                 : "r"(a0), "r"(a1), "r"(a2), "r"(a3), "r"(b0), "r"(b1))

// smem layout (dynamic):
//   [0:512)     toks
//   [512:1024)  wts
//   [1024:...)  per-buffer matrices, row stride 80B (32+8 bf16 pad):
//     Abase(buf,h) = 1024 + buf*40960 + h*10240     (A: 128 x 40 bf16)
//     Bbase(buf,h) = 1024 + buf*40960 + 20480 + h*10240
#define SM_MAT    1024
#define HALF_SZ   10240
#define BUF_SZ    40960
#define ROWB      80
#define SMEM_TOTAL (SM_MAT + 2 * BUF_SZ)   // 82944

__global__ void zero_cnt_kernel() {
    if (threadIdx.x < NEXP) g_cnt[threadIdx.x] = 0;
}

__global__ __launch_bounds__(256) void gate_route_kernel(
    const float* __restrict__ x, const float* __restrict__ gw)
{
    int warp = threadIdx.x >> 5, lane = threadIdx.x & 31;
    int n = blockIdx.x * 8 + warp;
    if (n >= N_TOK) return;
    const float* xr = x + (size_t)n * DDIM;

    float acc[NEXP];
#pragma unroll
    for (int e = 0; e < NEXP; e++) acc[e] = 0.f;
    for (int d = lane; d < DDIM; d += 32) {
        float xv = xr[d];
        const float* g = gw + d * NEXP;
#pragma unroll
        for (int e = 0; e < NEXP; e++) acc[e] = fmaf(xv, g[e], acc[e]);
    }
#pragma unroll
    for (int e = 0; e < NEXP; e++) {
#pragma unroll
        for (int o = 16; o > 0; o >>= 1)
            acc[e] += __shfl_xor_sync(0xFFFFFFFFu, acc[e], o);
    }
    if (lane == 0) {
        int e0 = 0; float l0 = acc[0];
#pragma unroll
        for (int e = 1; e < NEXP; e++) if (acc[e] > l0) { l0 = acc[e]; e0 = e; }
        int e1 = -1; float l1 = -INFINITY;
#pragma unroll
        for (int e = 0; e < NEXP; e++)
            if (e != e0 && acc[e] > l1) { l1 = acc[e]; e1 = e; }
        float tt  = expf(l1 - l0);
        float inv = 1.f / (1.f + tt);
        int p0 = atomicAdd(&g_cnt[e0], 1);
        g_tok[e0 * N_TOK + p0] = 2 * n;
        g_wt [e0 * N_TOK + p0] = inv;
        int p1 = atomicAdd(&g_cnt[e1], 1);
        g_tok[e1 * N_TOK + p1] = 2 * n + 1;
        g_wt [e1 * N_TOK + p1] = tt * inv;
    }
}

__global__ __launch_bounds__(256) void convert_x_kernel(const float* __restrict__ x)
{
    size_t i = ((size_t)blockIdx.x * 256 + threadIdx.x) * 4;
    float4 v = *(const float4*)(x + i);
    __nv_bfloat16 h[4], l[4];
    float vv[4] = {v.x, v.y, v.z, v.w};
#pragma unroll
    for (int j = 0; j < 4; j++) {
        h[j] = __float2bfloat16(vv[j]);
        l[j] = __float2bfloat16(vv[j] - __bfloat162float(h[j]));
    }
    *(uint2*)(g_xhi + i) = *(uint2*)h;
    *(uint2*)(g_xlo + i) = *(uint2*)l;
}

__global__ __launch_bounds__(256) void convert_w_kernel(const float* __restrict__ w)
{
    __shared__ float tile[32][33];
    int e  = blockIdx.z;
    int k0 = blockIdx.x * 32, n0 = blockIdx.y * 32;
    int tx = threadIdx.x & 31, ty = threadIdx.x >> 5;
    const float* src = w + ((size_t)e * DDIM + k0) * DDIM + n0;
#pragma unroll
    for (int i = 0; i < 4; i++) {
        int kk = ty + i * 8;
        tile[kk][tx] = src[(size_t)kk * DDIM + tx];
    }
    __syncthreads();
    size_t ob = ((size_t)e * DDIM + n0) * DDIM + k0;
#pragma unroll
    for (int i = 0; i < 4; i++) {
        int nn = ty + i * 8;
        float v = tile[tx][nn];
        __nv_bfloat16 h = __float2bfloat16(v);
        __nv_bfloat16 l = __float2bfloat16(v - __bfloat162float(h));
        g_whi[ob + (size_t)nn * DDIM + tx] = h;
        g_wlo[ob + (size_t)nn * DDIM + tx] = l;
    }
}

// Grouped GEMM on mma.sync bf16 (HMMA path; tcgen05 unavailable under the
// harness's compute_103 PTX target). 128x128 tile, BK=16, 8 warps (2x4),
// warp tile 64x32, hi/lo split = 3 MMAs per fragment pair, fp32 accum.
__global__ __launch_bounds__(256, 1) void moe_gemm_mma(const float* __restrict__ eb)
{
    extern __shared__ char smem[];
    int e   = blockIdx.z;
    int cnt = g_cnt[e];
    int m0  = blockIdx.y * TM;
    if (m0 >= cnt) return;
    int n0  = blockIdx.x * TN;

    int t = threadIdx.x, wid = t >> 5, lid = t & 31;
    int warp_m = wid & 1, warp_n = wid >> 1;

    int*   toks = (int*)  (smem);
    float* wts  = (float*)(smem + 512);
    if (t < TM) {
        int r = m0 + t;
        bool ok = (r < cnt);
        toks[t] = ok ? g_tok[e * N_TOK + r] : 0;
        wts [t] = ok ? g_wt [e * N_TOK + r] : 0.f;
    }
    __syncthreads();

    // loaders: threads 0-127 hi, 128-255 lo; one row (of 128) each
    int  lrow = t & 127;
    bool isLo = (t >= 128);
    const __nv_bfloat16* ap =
        (isLo ? g_xlo : g_xhi) + (size_t)(toks[lrow] >> 1) * DDIM;
    const __nv_bfloat16* bp =
        (isLo ? g_wlo : g_whi) + ((size_t)e * DDIM + n0 + lrow) * DDIM;
    char* aS = smem + SM_MAT + (isLo ? HALF_SZ : 0);
    char* bS = smem + SM_MAT + 20480 + (isLo ? HALF_SZ : 0);
    int rowbyte = lrow * ROWB;

    // prologue: chunk 0 -> buffer 0
    {
        uint4 a0 = *(const uint4*)(ap);
        uint4 a1 = *(const uint4*)(ap + 8);
        uint4 b0 = *(const uint4*)(bp);
        uint4 b1 = *(const uint4*)(bp + 8);
        *(uint4*)(aS + rowbyte)      = a0;
        *(uint4*)(aS + rowbyte + 16) = a1;
        *(uint4*)(bS + rowbyte)      = b0;
        *(uint4*)(bS + rowbyte + 16) = b1;
    }
    __syncthreads();

    float acc[4][4][4];
#pragma unroll
    for (int i = 0; i < 4; i++)
#pragma unroll
        for (int j = 0; j < 4; j++)
#pragma unroll
            for (int q = 0; q < 4; q++) acc[i][j][q] = 0.f;

    // ldmatrix lane offsets
    int grp = lid >> 3, li = lid & 7;
    // A tile i: groups (m+0,k0),(m+8,k0),(m+0,k8),(m+8,k8)
    uint32_t aLane = (uint32_t)((warp_m * 64 + (grp & 1) * 8 + li) * ROWB
                                + (grp >> 1) * 16);
    // B pair j2: groups (n+0,k0),(n+0,k8),(n+8,k0),(n+8,k8)
    uint32_t bLane = (uint32_t)((warp_n * 32 + (grp >> 1) * 8 + li) * ROWB
                                + (grp & 1) * 16);

    uint32_t sbase = smem_u32(smem) + SM_MAT;

    for (int it = 0; it < NT; it++) {
        int buf = it & 1;
        uint4 a0, a1, b0, b1;
        bool nx = (it + 1 < NT);
        if (nx) {
            const __nv_bfloat16* a = ap + (it + 1) * BK;
            const __nv_bfloat16* b = bp + (it + 1) * BK;
            a0 = *(const uint4*)(a);
            a1 = *(const uint4*)(a + 8);
            b0 = *(const uint4*)(b);
            b1 = *(const uint4*)(b + 8);
        }

        uint32_t aB = sbase + buf * BUF_SZ;
        uint32_t bB = aB + 20480;

        // B fragments: 2 pairs x (hi, lo)
        uint32_t bh[8], bl[8];
#pragma unroll
        for (int j2 = 0; j2 < 2; j2++) {
            LDSM4(bh[j2*4+0], bh[j2*4+1], bh[j2*4+2], bh[j2*4+3],
                  bB + bLane + (uint32_t)(j2 * 16 * ROWB));
            LDSM4(bl[j2*4+0], bl[j2*4+1], bl[j2*4+2], bl[j2*4+3],
                  bB + HALF_SZ + bLane + (uint32_t)(j2 * 16 * ROWB));
        }

#pragma unroll
        for (int i = 0; i < 4; i++) {
            uint32_t ah0, ah1, ah2, ah3, al0, al1, al2, al3;
            LDSM4(ah0, ah1, ah2, ah3, aB + aLane + (uint32_t)(i * 16 * ROWB));
            LDSM4(al0, al1, al2, al3,
                  aB + HALF_SZ + aLane + (uint32_t)(i * 16 * ROWB));
#pragma unroll
            for (int j = 0; j < 4; j++) {
                int bi = (j >> 1) * 4 + (j & 1) * 2;
                MMA16816(acc[i][j], ah0, ah1, ah2, ah3, bh[bi], bh[bi+1]);
                MMA16816(acc[i][j], ah0, ah1, ah2, ah3, bl[bi], bl[bi+1]);
                MMA16816(acc[i][j], al0, al1, al2, al3, bh[bi], bh[bi+1]);
            }
        }

        if (nx) {
            __syncthreads();   // all reads of buf^1 (from it-1) are done
            int nb = buf ^ 1;
            char* ad = aS + nb * BUF_SZ + rowbyte;
            char* bd = bS + nb * BUF_SZ + rowbyte;
            *(uint4*)(ad)      = a0;
            *(uint4*)(ad + 16) = a1;
            *(uint4*)(bd)      = b0;
            *(uint4*)(bd + 16) = b1;
            __syncthreads();
        }
    }

    // epilogue: c0=C[g][2tg], c1=C[g][2tg+1], c2=C[g+8][2tg], c3=C[g+8][2tg+1]
    int g = lid >> 2, tg = lid & 3;
    float2 bias2[4];
#pragma unroll
    for (int j = 0; j < 4; j++) {
        int col = n0 + warp_n * 32 + j * 8 + tg * 2;
        bias2[j] = *(const float2*)(eb + (size_t)e * DDIM + col);
    }
#pragma unroll
    for (int i = 0; i < 4; i++) {
        int lr0 = warp_m * 64 + i * 16 + g;
        int lr1 = lr0 + 8;
        bool ok0 = (m0 + lr0) < cnt;
        bool ok1 = (m0 + lr1) < cnt;
        int   v0 = toks[lr0], v1 = toks[lr1];
        float w0 = wts [lr0], w1 = wts [lr1];
#pragma unroll
        for (int j = 0; j < 4; j++) {
            int col = n0 + warp_n * 32 + j * 8 + tg * 2;
            if (ok0) {
                float2 o;
                o.x = w0 * (acc[i][j][0] + bias2[j].x);
                o.y = w0 * (acc[i][j][1] + bias2[j].y);
                *(float2*)(g_scr + (size_t)v0 * DDIM + col) = o;
            }
            if (ok1) {
                float2 o;
                o.x = w1 * (acc[i][j][2] + bias2[j].x);
                o.y = w1 * (acc[i][j][3] + bias2[j].y);
                *(float2*)(g_scr + (size_t)v1 * DDIM + col) = o;
            }
        }
    }
}

__global__ __launch_bounds__(256) void combine_kernel(float* __restrict__ out)
{
    size_t i = (size_t)blockIdx.x * 256 + threadIdx.x;
    size_t n = i >> 9;
    size_t h = (i & 511) * 4;
    const float4 a = *(const float4*)(g_scr + (2 * n)     * (size_t)DDIM + h);
    const float4 b = *(const float4*)(g_scr + (2 * n + 1) * (size_t)DDIM + h);
    float4 o;
    o.x = a.x + b.x; o.y = a.y + b.y; o.z = a.z + b.z; o.w = a.w + b.w;
    *(float4*)(out + n * (size_t)DDIM + h) = o;
}

extern "C" void kernel_launch(void* const* d_in, const int* in_sizes, int n_in,
                              void* d_out, int out_size)
{
    const float* inputs   = (const float*)d_in[0];  // [N, D]
    const float* gate_w   = (const float*)d_in[1];  // [D, E]
    const float* expert_w = (const float*)d_in[2];  // [E, D, D]
    const float* expert_b = (const float*)d_in[3];  // [E, D]
    float* out = (float*)d_out;

    cudaFuncSetAttribute(moe_gemm_mma,
                         cudaFuncAttributeMaxDynamicSharedMemorySize, SMEM_TOTAL);

    zero_cnt_kernel<<<1, 32>>>();
    gate_route_kernel<<<N_TOK / 8, 256>>>(inputs, gate_w);
    convert_x_kernel<<<(int)(((size_t)N_TOK * DDIM / 4) / 256), 256>>>(inputs);
    dim3 wgrid(DDIM / 32, DDIM / 32, NEXP);
    convert_w_kernel<<<wgrid, 256>>>(expert_w);
    dim3 ggrid(DDIM / TN, N_TOK / TM, NEXP);
    moe_gemm_mma<<<ggrid, 256, SMEM_TOTAL>>>(expert_b);
    combine_kernel<<<(int)(((size_t)N_TOK * (DDIM / 4)) / 256), 256>>>(out);
}